// round 1
// baseline (speedup 1.0000x reference)
#include <cuda_runtime.h>
#include <math.h>

#define N 8192
#define D 128
#define NC 512
#define MAXM 64

// ---------------- scratch (device globals; no allocation allowed) ----------
__device__ float g_enorm[N * D];     // normalized embeddings
__device__ int   g_cnt[NC];          // class member counts
__device__ int   g_members[NC * MAXM];
__device__ float g_lsep[N];          // lse over positives (ap_term)
__device__ float g_samesum[N];       // sumexp(an_term) over same-class offdiag
__device__ float g_sall[N];          // sumexp(an_term) over all j != i
__device__ int   g_is64;             // labels dtype flag

__device__ __forceinline__ float an_exp(float s) {
    // an_term = SCALE * relu(s + MARGIN) * (s - MARGIN); clip -> term 0 -> exp 1
    float t = fmaxf(s + 0.4f, 0.0f);
    return __expf(80.0f * t * (s - 0.4f));
}

__device__ __forceinline__ int get_label(const void* lab, int i) {
    if (g_is64) return (int)((const long long*)lab)[i];
    return ((const int*)lab)[i];
}

// ---------------- kernel 0: init + dtype detect ----------------------------
__global__ void k_init(const void* lab) {
    int i = blockIdx.x * blockDim.x + threadIdx.x;
    if (i < N)  g_sall[i] = 0.0f;
    if (i < NC) g_cnt[i] = 0;
    if (blockIdx.x == 0 && threadIdx.x == 0) {
        // If labels are int64, every odd 32-bit word (high half) is 0.
        // 64 odd words all being 0 by chance under int32 is impossible here.
        const int* w = (const int*)lab;
        int is64 = 1;
        for (int k = 1; k < 128; k += 2)
            if (w[k] != 0) { is64 = 0; break; }
        g_is64 = is64;
    }
}

// ---------------- kernel 1: L2-normalize rows + class member lists ---------
__global__ void k_norm(const float* __restrict__ in, const void* __restrict__ lab) {
    int row  = blockIdx.x * 8 + (threadIdx.x >> 5);
    int lane = threadIdx.x & 31;
    float4 v = *(const float4*)(in + row * D + lane * 4);
    float ss = v.x * v.x + v.y * v.y + v.z * v.z + v.w * v.w;
    #pragma unroll
    for (int m = 16; m >= 1; m >>= 1) ss += __shfl_xor_sync(0xffffffffu, ss, m);
    float nrm = fmaxf(sqrtf(ss), 1e-12f);
    float inv = 1.0f / nrm;
    float4 o;
    o.x = v.x * inv; o.y = v.y * inv; o.z = v.z * inv; o.w = v.w * inv;
    *(float4*)(g_enorm + row * D + lane * 4) = o;
    if (lane == 0) {
        int c = get_label(lab, row);
        int p = atomicAdd(&g_cnt[c], 1);
        if (p < MAXM) g_members[c * MAXM + p] = row;
    }
}

// ---------------- kernel 2: per-class positives (lse_p) + same-class an-sum
__global__ void k_class() {
    int c = blockIdx.x;
    __shared__ int   mlist[MAXM];
    __shared__ float se[MAXM * 129];      // 129 stride -> conflict-free column dots
    __shared__ float sap[MAXM];
    __shared__ float san[MAXM];
    int m = g_cnt[c];
    if (m > MAXM) m = MAXM;
    if (m == 0) return;                   // uniform across block
    int tid = threadIdx.x;
    if (tid < m) mlist[tid] = g_members[c * MAXM + tid];
    __syncthreads();
    for (int p = tid; p < m * D; p += blockDim.x) {
        int r = p >> 7, k = p & 127;
        se[r * 129 + k] = g_enorm[mlist[r] * D + k];
    }
    __syncthreads();
    for (int a = 0; a < m; a++) {
        float ap = -1e30f, anx = 0.0f;
        if (tid < m && tid != a) {
            float s = 0.0f;
            #pragma unroll 8
            for (int k = 0; k < D; k++) s += se[a * 129 + k] * se[tid * 129 + k];
            float apa = fmaxf(1.4f - s, 0.0f);
            ap  = -80.0f * apa * (s - 0.6f);   // -SCALE*alpha*(s-1+MARGIN)
            anx = an_exp(s);
        }
        if (tid < MAXM) { sap[tid] = ap; san[tid] = anx; }
        __syncthreads();
        if (tid == 0) {
            float lse = 0.0f, ssum = 0.0f;
            if (m > 1) {
                float mx = -1e30f;
                for (int b = 0; b < m; b++) mx = fmaxf(mx, sap[b]);
                float es = 0.0f;
                for (int b = 0; b < m; b++) {
                    if (b != a) es += __expf(sap[b] - mx);
                    ssum += san[b];
                }
                lse = mx + logf(es);
            }
            g_lsep[mlist[a]]    = lse;
            g_samesum[mlist[a]] = ssum;
        }
        __syncthreads();
    }
}

// ---------------- kernel 3: symmetric tiled SGEMM + fused an-sumexp --------
#define BM 128
#define BN 128
#define BK 16
__global__ __launch_bounds__(256, 2) void k_main() {
    int bi = blockIdx.y, bj = blockIdx.x;
    if (bj < bi) return;                   // upper triangle only (symmetry)
    __shared__ float As[BK][BM + 4];
    __shared__ float Bs[BK][BN + 4];
    __shared__ float redc[BN][17];
    int tid = threadIdx.x;
    int tx = tid & 15, ty = tid >> 4;
    int rowBase = bi * BM, colBase = bj * BN;
    float acc[8][8];
    #pragma unroll
    for (int u = 0; u < 8; u++)
        #pragma unroll
        for (int v = 0; v < 8; v++) acc[u][v] = 0.0f;

    int lr = tid >> 2;
    int lk = (tid & 3) << 2;
    const float* E = g_enorm;
    for (int kc = 0; kc < D; kc += BK) {
        #pragma unroll
        for (int s = 0; s < 2; s++) {
            int r = lr + s * 64;
            float4 va = *(const float4*)(E + (rowBase + r) * D + kc + lk);
            As[lk + 0][r] = va.x; As[lk + 1][r] = va.y;
            As[lk + 2][r] = va.z; As[lk + 3][r] = va.w;
            float4 vb = *(const float4*)(E + (colBase + r) * D + kc + lk);
            Bs[lk + 0][r] = vb.x; Bs[lk + 1][r] = vb.y;
            Bs[lk + 2][r] = vb.z; Bs[lk + 3][r] = vb.w;
        }
        __syncthreads();
        #pragma unroll
        for (int k = 0; k < BK; k++) {
            float a[8], b[8];
            #pragma unroll
            for (int u = 0; u < 8; u++) a[u] = As[k][ty * 8 + u];
            #pragma unroll
            for (int v = 0; v < 8; v++) b[v] = Bs[k][tx * 8 + v];
            #pragma unroll
            for (int u = 0; u < 8; u++)
                #pragma unroll
                for (int v = 0; v < 8; v++)
                    acc[u][v] = fmaf(a[u], b[v], acc[u][v]);
        }
        __syncthreads();
    }

    bool offdiag = (bi != bj);
    float rowsum[8], colsum[8];
    #pragma unroll
    for (int u = 0; u < 8; u++) rowsum[u] = 0.0f;
    #pragma unroll
    for (int v = 0; v < 8; v++) colsum[v] = 0.0f;
    #pragma unroll
    for (int u = 0; u < 8; u++) {
        int gi = rowBase + ty * 8 + u;
        #pragma unroll
        for (int v = 0; v < 8; v++) {
            int gj = colBase + tx * 8 + v;
            float e = an_exp(acc[u][v]);
            if (gi == gj) e = 0.0f;       // exclude diagonal
            rowsum[u] += e;
            colsum[v] += e;
        }
    }
    // row-sums: reduce across tx within each 16-lane half-warp
    #pragma unroll
    for (int u = 0; u < 8; u++) {
        float v = rowsum[u];
        #pragma unroll
        for (int msk = 8; msk >= 1; msk >>= 1)
            v += __shfl_xor_sync(0xffffffffu, v, msk);
        if (tx == 0) atomicAdd(&g_sall[rowBase + ty * 8 + u], v);
    }
    // col-sums (only for off-diagonal tiles): smem reduce across ty
    if (offdiag) {
        #pragma unroll
        for (int v = 0; v < 8; v++) redc[tx * 8 + v][ty] = colsum[v];
        __syncthreads();
        if (tid < BN) {
            float s = 0.0f;
            #pragma unroll
            for (int t = 0; t < 16; t++) s += redc[tid][t];
            atomicAdd(&g_sall[colBase + tid], s);
        }
    }
}

// ---------------- kernel 4: finalize loss ----------------------------------
__global__ void k_final(const void* __restrict__ lab, float* __restrict__ out) {
    __shared__ float ssum[256];
    __shared__ int   scnt[256];
    int tid = threadIdx.x;
    float acc = 0.0f;
    int cnt = 0;
    for (int i = tid; i < N; i += 256) {
        int c = get_label(lab, i);
        int m = g_cnt[c];
        int np = m - 1, nn = N - m;
        if (np > 0 && nn > 0) {
            float sneg = g_sall[i] - g_samesum[i];
            sneg = fmaxf(sneg, 1e-30f);
            float x = g_lsep[i] + logf((float)nn) + logf(sneg) + logf((float)np);
            float sp = (x > 0.0f) ? (x + log1pf(__expf(-x))) : log1pf(__expf(x));
            acc += sp;
            cnt++;
        }
    }
    ssum[tid] = acc; scnt[tid] = cnt;
    __syncthreads();
    for (int s = 128; s > 0; s >>= 1) {
        if (tid < s) { ssum[tid] += ssum[tid + s]; scnt[tid] += scnt[tid + s]; }
        __syncthreads();
    }
    if (tid == 0) out[0] = ssum[0] / fmaxf((float)scnt[0], 1.0f);
}

// ---------------- launch ---------------------------------------------------
extern "C" void kernel_launch(void* const* d_in, const int* in_sizes, int n_in,
                              void* d_out, int out_size) {
    const float* embeds = (const float*)d_in[0];
    const void*  labels = d_in[1];
    float* out = (float*)d_out;
    (void)in_sizes; (void)n_in; (void)out_size;

    k_init<<<32, 256>>>(labels);
    k_norm<<<N / 8, 256>>>(embeds, labels);
    k_class<<<NC, 128>>>();
    dim3 grid(N / BN, N / BM);
    k_main<<<grid, 256>>>();
    k_final<<<1, 256>>>(labels, out);
}

// round 3
// speedup vs baseline: 1.5746x; 1.5746x over previous
#include <cuda_runtime.h>
#include <cuda_bf16.h>
#include <math.h>
#include <stdint.h>

#define N 8192
#define D 128
#define NC 512
#define MAXM 64

// ---------------- scratch (device globals; no allocation allowed) ----------
__device__ __align__(16) float g_enorm[N * D];
__device__ __align__(16) __nv_bfloat16 g_hi[N * D];
__device__ __align__(16) __nv_bfloat16 g_mid[N * D];
__device__ int   g_cnt[NC];
__device__ int   g_members[NC * MAXM];
__device__ float g_lsep[N];
__device__ float g_samesum[N];
__device__ float g_sall[N];
__device__ int   g_is64;

__device__ __forceinline__ float an_exp(float s) {
    float t = fmaxf(s + 0.4f, 0.0f);
    return __expf(80.0f * t * (s - 0.4f));
}

__device__ __forceinline__ int get_label(const void* lab, int i) {
    if (g_is64) return (int)((const long long*)lab)[i];
    return ((const int*)lab)[i];
}

// ---------------- kernel 0: zero + dtype detect ----------------------------
__global__ void k_zero(const void* lab) {
    int i = blockIdx.x * blockDim.x + threadIdx.x;
    if (i < N)  g_sall[i] = 0.0f;
    if (i < NC) g_cnt[i] = 0;
    if (i == 0) {
        const int* w = (const int*)lab;
        int bad = 0;
        #pragma unroll
        for (int k = 1; k < 128; k += 2) bad |= w[k];
        g_is64 = (bad == 0);
    }
}

// ---------------- kernel 1: normalize + bf16 split + class lists -----------
__global__ void k_norm(const float* __restrict__ in, const void* __restrict__ lab) {
    int row  = blockIdx.x * 8 + (threadIdx.x >> 5);
    int lane = threadIdx.x & 31;
    float4 v = *(const float4*)(in + row * D + lane * 4);
    float ss = v.x * v.x + v.y * v.y + v.z * v.z + v.w * v.w;
    #pragma unroll
    for (int m = 16; m >= 1; m >>= 1) ss += __shfl_xor_sync(0xffffffffu, ss, m);
    float inv = 1.0f / fmaxf(sqrtf(ss), 1e-12f);
    float o[4] = {v.x * inv, v.y * inv, v.z * inv, v.w * inv};
    float4 of; of.x = o[0]; of.y = o[1]; of.z = o[2]; of.w = o[3];
    *(float4*)(g_enorm + row * D + lane * 4) = of;
    #pragma unroll
    for (int c = 0; c < 4; c++) {
        __nv_bfloat16 h = __float2bfloat16(o[c]);
        float r = o[c] - __bfloat162float(h);
        g_hi [row * D + lane * 4 + c] = h;
        g_mid[row * D + lane * 4 + c] = __float2bfloat16(r);
    }
    if (lane == 0) {
        int c = get_label(lab, row);
        int p = atomicAdd(&g_cnt[c], 1);
        if (p < MAXM) g_members[c * MAXM + p] = row;
    }
}

// ---------------- kernel 2: per-class positives (exact fp32) ---------------
__global__ void k_class() {
    int c = blockIdx.x;
    __shared__ int   mlist[MAXM];
    __shared__ float se[MAXM * 129];
    __shared__ float sap[MAXM];
    __shared__ float san[MAXM];
    int m = g_cnt[c];
    if (m > MAXM) m = MAXM;
    if (m == 0) return;
    int tid = threadIdx.x;
    if (tid < m) mlist[tid] = g_members[c * MAXM + tid];
    __syncthreads();
    for (int p = tid; p < m * D; p += blockDim.x) {
        int r = p >> 7, k = p & 127;
        se[r * 129 + k] = g_enorm[mlist[r] * D + k];
    }
    __syncthreads();
    for (int a = 0; a < m; a++) {
        float ap = -1e30f, anx = 0.0f;
        if (tid < m && tid != a) {
            float s = 0.0f;
            #pragma unroll 8
            for (int k = 0; k < D; k++) s += se[a * 129 + k] * se[tid * 129 + k];
            float apa = fmaxf(1.4f - s, 0.0f);
            ap  = -80.0f * apa * (s - 0.6f);
            anx = an_exp(s);
        }
        if (tid < MAXM) { sap[tid] = ap; san[tid] = anx; }
        __syncthreads();
        if (tid == 0) {
            float lse = 0.0f, ssum = 0.0f;
            if (m > 1) {
                float mx = -1e30f;
                for (int b = 0; b < m; b++) mx = fmaxf(mx, sap[b]);
                float es = 0.0f;
                for (int b = 0; b < m; b++) {
                    if (b != a) es += __expf(sap[b] - mx);
                    ssum += san[b];
                }
                lse = mx + logf(es);
            }
            g_lsep[mlist[a]]    = lse;
            g_samesum[mlist[a]] = ssum;
        }
        __syncthreads();
    }
}

// ---------------- kernel 3: mma.sync bf16-split GEMM + fused an-sumexp -----
// smem: 4 arrays of 128 rows x 64 halves, row stride 144 B (16B-aligned,
// conflict-free: 144*g mod 128 = 16*g -> distinct banks for g=0..7)
#define SROW   144
#define SA_HI  0
#define SA_MID (128 * SROW)
#define SB_HI  (2 * 128 * SROW)
#define SB_MID (3 * 128 * SROW)
#define SMEM_SZ (4 * 128 * SROW)   // 73728 B

__device__ __forceinline__ void mma_bf16(float* d, const uint32_t* a, const uint32_t* b) {
    asm volatile(
        "mma.sync.aligned.m16n8k16.row.col.f32.bf16.bf16.f32 "
        "{%0,%1,%2,%3}, {%4,%5,%6,%7}, {%8,%9}, {%0,%1,%2,%3};\n"
        : "+f"(d[0]), "+f"(d[1]), "+f"(d[2]), "+f"(d[3])
        : "r"(a[0]), "r"(a[1]), "r"(a[2]), "r"(a[3]), "r"(b[0]), "r"(b[1]));
}

__device__ __forceinline__ void load_tile(char* dst, const __nv_bfloat16* src,
                                          int baseRow, int kc, int tid) {
    const uint4* g = (const uint4*)(src + (size_t)baseRow * D + kc * 64);
    #pragma unroll
    for (int it = 0; it < 4; it++) {
        int idx = it * 256 + tid;          // 0..1023
        int row = idx >> 3, k8 = idx & 7;  // row stride in gmem = 16 uint4
        uint4 v = g[row * 16 + k8];
        *(uint4*)(dst + row * SROW + k8 * 16) = v;
    }
}

__global__ void __launch_bounds__(256, 2) k_main_m() {
    int bi = blockIdx.y, bj = blockIdx.x;
    if (bj < bi) return;                   // symmetry: upper triangle only
    extern __shared__ char sm[];
    int tid = threadIdx.x;
    int lane = tid & 31, wid = tid >> 5;
    int g = lane >> 2, t = lane & 3;
    int wm = wid & 3, wn = wid >> 2;       // 4x2 warp grid, warp tile 32x64
    int rowBase = bi * 128, colBase = bj * 128;

    float acc[2][8][4];
    #pragma unroll
    for (int i = 0; i < 2; i++)
        #pragma unroll
        for (int j = 0; j < 8; j++)
            #pragma unroll
            for (int e = 0; e < 4; e++) acc[i][j][e] = 0.0f;

    for (int kc = 0; kc < 2; kc++) {
        load_tile(sm + SA_HI,  g_hi,  rowBase, kc, tid);
        load_tile(sm + SA_MID, g_mid, rowBase, kc, tid);
        load_tile(sm + SB_HI,  g_hi,  colBase, kc, tid);
        load_tile(sm + SB_MID, g_mid, colBase, kc, tid);
        __syncthreads();
        #pragma unroll
        for (int ks = 0; ks < 4; ks++) {
            int k0b = ks * 32 + t * 4;     // byte offset of halves (ks*16 + 2t)
            uint32_t ahi[2][4], amid[2][4];
            #pragma unroll
            for (int i = 0; i < 2; i++) {
                int r0 = (wm * 32 + i * 16 + g) * SROW + k0b;
                int r1 = r0 + 8 * SROW;
                ahi[i][0]  = *(const uint32_t*)(sm + SA_HI  + r0);
                ahi[i][1]  = *(const uint32_t*)(sm + SA_HI  + r1);
                ahi[i][2]  = *(const uint32_t*)(sm + SA_HI  + r0 + 16);
                ahi[i][3]  = *(const uint32_t*)(sm + SA_HI  + r1 + 16);
                amid[i][0] = *(const uint32_t*)(sm + SA_MID + r0);
                amid[i][1] = *(const uint32_t*)(sm + SA_MID + r1);
                amid[i][2] = *(const uint32_t*)(sm + SA_MID + r0 + 16);
                amid[i][3] = *(const uint32_t*)(sm + SA_MID + r1 + 16);
            }
            #pragma unroll
            for (int j = 0; j < 8; j++) {
                int c0 = (wn * 64 + j * 8 + g) * SROW + k0b;
                uint32_t bhi[2], bmid[2];
                bhi[0]  = *(const uint32_t*)(sm + SB_HI  + c0);
                bhi[1]  = *(const uint32_t*)(sm + SB_HI  + c0 + 16);
                bmid[0] = *(const uint32_t*)(sm + SB_MID + c0);
                bmid[1] = *(const uint32_t*)(sm + SB_MID + c0 + 16);
                #pragma unroll
                for (int i = 0; i < 2; i++) {
                    mma_bf16(acc[i][j], ahi[i],  bhi);   // hh
                    mma_bf16(acc[i][j], amid[i], bhi);   // mh
                    mma_bf16(acc[i][j], ahi[i],  bmid);  // hm
                }
            }
        }
        __syncthreads();
    }

    bool diag = (bi == bj);
    // exp(an_term), diagonal masked; overwrite acc in place
    #pragma unroll
    for (int i = 0; i < 2; i++)
        #pragma unroll
        for (int j = 0; j < 8; j++)
            #pragma unroll
            for (int e = 0; e < 4; e++) {
                float x = an_exp(acc[i][j][e]);
                if (diag) {
                    int rl = wm * 32 + i * 16 + g + ((e >> 1) << 3);
                    int cl = wn * 64 + j * 8 + 2 * t + (e & 1);
                    if (rl == cl) x = 0.0f;
                }
                acc[i][j][e] = x;
            }
    // row sums: reduce over n within thread, then over t (lanes xor 1,2)
    #pragma unroll
    for (int i = 0; i < 2; i++)
        #pragma unroll
        for (int h = 0; h < 2; h++) {
            float v = 0.0f;
            #pragma unroll
            for (int j = 0; j < 8; j++) v += acc[i][j][2 * h] + acc[i][j][2 * h + 1];
            v += __shfl_xor_sync(0xffffffffu, v, 1);
            v += __shfl_xor_sync(0xffffffffu, v, 2);
            if (t == 0)
                atomicAdd(&g_sall[rowBase + wm * 32 + i * 16 + g + h * 8], v);
        }
    // col sums (transpose contributions), only off-diagonal tiles
    if (!diag) {
        #pragma unroll
        for (int j = 0; j < 8; j++)
            #pragma unroll
            for (int b = 0; b < 2; b++) {
                float v = acc[0][j][b] + acc[0][j][2 + b] +
                          acc[1][j][b] + acc[1][j][2 + b];
                v += __shfl_xor_sync(0xffffffffu, v, 4);
                v += __shfl_xor_sync(0xffffffffu, v, 8);
                v += __shfl_xor_sync(0xffffffffu, v, 16);
                if (g == 0)
                    atomicAdd(&g_sall[colBase + wn * 64 + j * 8 + 2 * t + b], v);
            }
    }
}

// ---------------- kernel 4: finalize loss ----------------------------------
__global__ void k_final(const void* __restrict__ lab, float* __restrict__ out) {
    __shared__ float ssum[256];
    __shared__ int   scnt[256];
    int tid = threadIdx.x;
    float acc = 0.0f;
    int cnt = 0;
    for (int i = tid; i < N; i += 256) {
        int c = get_label(lab, i);
        int m = g_cnt[c];
        int np = m - 1, nn = N - m;
        if (np > 0 && nn > 0) {
            float sneg = g_sall[i] - g_samesum[i];
            sneg = fmaxf(sneg, 1e-30f);
            float x = g_lsep[i] + logf((float)nn) + logf(sneg) + logf((float)np);
            float sp = (x > 0.0f) ? (x + log1pf(__expf(-x))) : log1pf(__expf(x));
            acc += sp;
            cnt++;
        }
    }
    ssum[tid] = acc; scnt[tid] = cnt;
    __syncthreads();
    for (int s = 128; s > 0; s >>= 1) {
        if (tid < s) { ssum[tid] += ssum[tid + s]; scnt[tid] += scnt[tid + s]; }
        __syncthreads();
    }
    if (tid == 0) out[0] = ssum[0] / fmaxf((float)scnt[0], 1.0f);
}

// ---------------- launch ---------------------------------------------------
extern "C" void kernel_launch(void* const* d_in, const int* in_sizes, int n_in,
                              void* d_out, int out_size) {
    const float* embeds = (const float*)d_in[0];
    const void*  labels = d_in[1];
    float* out = (float*)d_out;
    (void)in_sizes; (void)n_in; (void)out_size;

    cudaFuncSetAttribute(k_main_m, cudaFuncAttributeMaxDynamicSharedMemorySize, SMEM_SZ);

    k_zero<<<32, 256>>>(labels);
    k_norm<<<N / 8, 256>>>(embeds, labels);
    k_class<<<NC, 128>>>();
    dim3 grid(64, 64);
    k_main_m<<<grid, 256, SMEM_SZ>>>();
    k_final<<<1, 256>>>(labels, out);
}

// round 4
// speedup vs baseline: 2.1407x; 1.3595x over previous
#include <cuda_runtime.h>
#include <cuda_bf16.h>
#include <math.h>
#include <stdint.h>

#define N 8192
#define D 128
#define NC 512
#define MAXM 64

// ---------------- scratch (device globals; no allocation allowed) ----------
__device__ __align__(16) float g_enorm[N * D];
__device__ __align__(16) __nv_bfloat16 g_hi[N * D];
__device__ __align__(16) __nv_bfloat16 g_mid[N * D];
__device__ int   g_cnt[NC];
__device__ int   g_members[NC * MAXM];
__device__ float g_lsep[N];
__device__ float g_samesum[N];
__device__ float g_sall[N];
__device__ int   g_is64;

__device__ __forceinline__ float an_exp(float s) {
    float t = fmaxf(s + 0.4f, 0.0f);
    return __expf(80.0f * t * (s - 0.4f));
}

__device__ __forceinline__ int get_label(const void* lab, int i) {
    if (g_is64) return (int)((const long long*)lab)[i];
    return ((const int*)lab)[i];
}

__device__ __forceinline__ uint32_t smem_u32(const void* p) {
    uint32_t a;
    asm("{ .reg .u64 t; cvta.to.shared.u64 t, %1; cvt.u32.u64 %0, t; }" : "=r"(a) : "l"(p));
    return a;
}
__device__ __forceinline__ void cpa16(uint32_t dst, const void* src) {
    asm volatile("cp.async.cg.shared.global [%0], [%1], 16;" :: "r"(dst), "l"(src) : "memory");
}
__device__ __forceinline__ void ldsm4(uint32_t* r, uint32_t addr) {
    asm volatile("ldmatrix.sync.aligned.m8n8.x4.shared.b16 {%0,%1,%2,%3}, [%4];"
        : "=r"(r[0]), "=r"(r[1]), "=r"(r[2]), "=r"(r[3]) : "r"(addr));
}
__device__ __forceinline__ void mma_bf16(float* d, const uint32_t* a, uint32_t b0, uint32_t b1) {
    asm volatile(
        "mma.sync.aligned.m16n8k16.row.col.f32.bf16.bf16.f32 "
        "{%0,%1,%2,%3}, {%4,%5,%6,%7}, {%8,%9}, {%0,%1,%2,%3};\n"
        : "+f"(d[0]), "+f"(d[1]), "+f"(d[2]), "+f"(d[3])
        : "r"(a[0]), "r"(a[1]), "r"(a[2]), "r"(a[3]), "r"(b0), "r"(b1));
}

// ---------------- kernel 0: tiny pre (g_cnt zero + dtype flag) -------------
__global__ void k_pre(const void* lab) {
    int i = blockIdx.x * blockDim.x + threadIdx.x;
    if (i < NC) g_cnt[i] = 0;
    if (i == 0) {
        const int* w = (const int*)lab;
        int bad = 0;
        #pragma unroll
        for (int k = 1; k < 128; k += 2) bad |= w[k];
        g_is64 = (bad == 0);
    }
}

// ---------------- kernel 1: normalize + bf16 split + lists + zero sall -----
__global__ void k_norm(const float* __restrict__ in, const void* __restrict__ lab) {
    int gid = blockIdx.x * blockDim.x + threadIdx.x;
    if (gid < N) g_sall[gid] = 0.0f;
    int row  = blockIdx.x * 8 + (threadIdx.x >> 5);
    int lane = threadIdx.x & 31;
    float4 v = *(const float4*)(in + row * D + lane * 4);
    float ss = v.x * v.x + v.y * v.y + v.z * v.z + v.w * v.w;
    #pragma unroll
    for (int m = 16; m >= 1; m >>= 1) ss += __shfl_xor_sync(0xffffffffu, ss, m);
    float inv = 1.0f / fmaxf(sqrtf(ss), 1e-12f);
    float o[4] = {v.x * inv, v.y * inv, v.z * inv, v.w * inv};
    float4 of; of.x = o[0]; of.y = o[1]; of.z = o[2]; of.w = o[3];
    *(float4*)(g_enorm + row * D + lane * 4) = of;
    #pragma unroll
    for (int c = 0; c < 4; c++) {
        __nv_bfloat16 h = __float2bfloat16(o[c]);
        float r = o[c] - __bfloat162float(h);
        g_hi [row * D + lane * 4 + c] = h;
        g_mid[row * D + lane * 4 + c] = __float2bfloat16(r);
    }
    if (lane == 0) {
        int c = get_label(lab, row);
        int p = atomicAdd(&g_cnt[c], 1);
        if (p < MAXM) g_members[c * MAXM + p] = row;
    }
}

// ---------------- kernel 2: per-class positives, warp-per-anchor -----------
__global__ void k_class() {
    int c = blockIdx.x;
    __shared__ int   mlist[MAXM];
    __shared__ float se[MAXM * 129];
    int m = g_cnt[c];
    if (m > MAXM) m = MAXM;
    if (m == 0) return;
    int tid = threadIdx.x, lane = tid & 31, wid = tid >> 5;
    if (tid < m) mlist[tid] = g_members[c * MAXM + tid];
    __syncthreads();
    for (int p = tid; p < m * D; p += blockDim.x) {
        int r = p >> 7, k = p & 127;
        se[r * 129 + k] = g_enorm[mlist[r] * D + k];
    }
    __syncthreads();
    for (int a = wid; a < m; a += 4) {
        int b0 = lane, b1 = lane + 32;
        float s0 = 0.0f, s1 = 0.0f;
        const float* ra = se + a * 129;
        #pragma unroll 8
        for (int k = 0; k < D; k++) {
            float av = ra[k];
            s0 = fmaf(av, se[b0 * 129 + k], s0);
            s1 = fmaf(av, se[b1 * 129 + k], s1);
        }
        float ap0 = -1e30f, ap1 = -1e30f, an0 = 0.0f, an1 = 0.0f;
        bool v0 = (b0 < m && b0 != a), v1 = (b1 < m && b1 != a);
        if (v0) { ap0 = -80.0f * fmaxf(1.4f - s0, 0.0f) * (s0 - 0.6f); an0 = an_exp(s0); }
        if (v1) { ap1 = -80.0f * fmaxf(1.4f - s1, 0.0f) * (s1 - 0.6f); an1 = an_exp(s1); }
        float mx = fmaxf(ap0, ap1);
        #pragma unroll
        for (int k = 16; k >= 1; k >>= 1) mx = fmaxf(mx, __shfl_xor_sync(0xffffffffu, mx, k));
        float es = (v0 ? __expf(ap0 - mx) : 0.0f) + (v1 ? __expf(ap1 - mx) : 0.0f);
        float sa = an0 + an1;
        #pragma unroll
        for (int k = 16; k >= 1; k >>= 1) {
            es += __shfl_xor_sync(0xffffffffu, es, k);
            sa += __shfl_xor_sync(0xffffffffu, sa, k);
        }
        if (lane == 0) {
            g_lsep[mlist[a]]    = mx + logf(es);
            g_samesum[mlist[a]] = sa;
        }
    }
}

// ---------------- kernel 3: mma.sync + ldmatrix + cp.async -----------------
#define SROW   144
#define SA_HI  0
#define SA_MID (128 * SROW)
#define SB_HI  (2 * 128 * SROW)
#define SB_MID (3 * 128 * SROW)
#define SMEM_SZ (4 * 128 * SROW)   // 73728 B

__global__ void __launch_bounds__(256, 2) k_main_m() {
    // triangular decode: block b -> (bi, bj) with bi <= bj
    int b = blockIdx.x;
    int r = (int)((__fsqrt_rn(8.0f * (float)b + 1.0f) - 1.0f) * 0.5f);
    while ((r + 1) * (r + 2) / 2 <= b) r++;
    while (r * (r + 1) / 2 > b) r--;
    int bi = b - r * (r + 1) / 2;
    int bj = r;

    extern __shared__ char sm[];
    uint32_t sb = smem_u32(sm);
    int tid = threadIdx.x;
    int lane = tid & 31, wid = tid >> 5;
    int g = lane >> 2, t = lane & 3;
    int wm = wid & 3, wn = wid >> 2;       // 4x2 warp grid, warp tile 32x64
    int rowBase = bi * 128, colBase = bj * 128;

    // ldmatrix per-lane offset: row (lane&15), halfword group (lane>>4)
    uint32_t lmo = (uint32_t)((lane & 15) * SROW + (lane >> 4) * 16);
    uint32_t aBaseHi  = sb + SA_HI  + (uint32_t)(wm * 32) * SROW + lmo;
    uint32_t aBaseMid = sb + SA_MID + (uint32_t)(wm * 32) * SROW + lmo;
    uint32_t bBaseHi  = sb + SB_HI  + (uint32_t)(wn * 64) * SROW + lmo;
    uint32_t bBaseMid = sb + SB_MID + (uint32_t)(wn * 64) * SROW + lmo;

    float acc[2][8][4];
    #pragma unroll
    for (int i = 0; i < 2; i++)
        #pragma unroll
        for (int j = 0; j < 8; j++)
            #pragma unroll
            for (int e = 0; e < 4; e++) acc[i][j][e] = 0.0f;

    for (int kc = 0; kc < 2; kc++) {
        // ---- async tile loads: 4 arrays x 1024 uint4 ----
        #pragma unroll
        for (int it = 0; it < 4; it++) {
            int idx = it * 256 + tid;
            int row = idx >> 3, k8 = idx & 7;
            uint32_t so = (uint32_t)(row * SROW + k8 * 16);
            size_t gA = (size_t)(rowBase + row) * 16 + kc * 8 + k8;
            size_t gB = (size_t)(colBase + row) * 16 + kc * 8 + k8;
            cpa16(sb + SA_HI  + so, (const uint4*)g_hi  + gA);
            cpa16(sb + SA_MID + so, (const uint4*)g_mid + gA);
            cpa16(sb + SB_HI  + so, (const uint4*)g_hi  + gB);
            cpa16(sb + SB_MID + so, (const uint4*)g_mid + gB);
        }
        asm volatile("cp.async.commit_group;" ::: "memory");
        asm volatile("cp.async.wait_group 0;" ::: "memory");
        __syncthreads();

        #pragma unroll
        for (int ks = 0; ks < 4; ks++) {
            uint32_t ko = (uint32_t)(ks * 32);
            uint32_t ah[2][4], am[2][4];
            ldsm4(ah[0], aBaseHi  + ko);
            ldsm4(ah[1], aBaseHi  + ko + 16 * SROW);
            ldsm4(am[0], aBaseMid + ko);
            ldsm4(am[1], aBaseMid + ko + 16 * SROW);
            #pragma unroll
            for (int jp = 0; jp < 4; jp++) {
                uint32_t bh[4], bm[4];
                ldsm4(bh, bBaseHi  + ko + (uint32_t)(jp * 16) * SROW);
                ldsm4(bm, bBaseMid + ko + (uint32_t)(jp * 16) * SROW);
                #pragma unroll
                for (int i = 0; i < 2; i++) {
                    mma_bf16(acc[i][2 * jp],     ah[i], bh[0], bh[2]);
                    mma_bf16(acc[i][2 * jp],     am[i], bh[0], bh[2]);
                    mma_bf16(acc[i][2 * jp],     ah[i], bm[0], bm[2]);
                    mma_bf16(acc[i][2 * jp + 1], ah[i], bh[1], bh[3]);
                    mma_bf16(acc[i][2 * jp + 1], am[i], bh[1], bh[3]);
                    mma_bf16(acc[i][2 * jp + 1], ah[i], bm[1], bm[3]);
                }
            }
        }
        __syncthreads();
    }

    bool diag = (bi == bj);
    #pragma unroll
    for (int i = 0; i < 2; i++)
        #pragma unroll
        for (int j = 0; j < 8; j++)
            #pragma unroll
            for (int e = 0; e < 4; e++) {
                float x = an_exp(acc[i][j][e]);
                if (diag) {
                    int rl = wm * 32 + i * 16 + g + ((e >> 1) << 3);
                    int cl = wn * 64 + j * 8 + 2 * t + (e & 1);
                    if (rl == cl) x = 0.0f;
                }
                acc[i][j][e] = x;
            }
    // row sums
    #pragma unroll
    for (int i = 0; i < 2; i++)
        #pragma unroll
        for (int h = 0; h < 2; h++) {
            float v = 0.0f;
            #pragma unroll
            for (int j = 0; j < 8; j++) v += acc[i][j][2 * h] + acc[i][j][2 * h + 1];
            v += __shfl_xor_sync(0xffffffffu, v, 1);
            v += __shfl_xor_sync(0xffffffffu, v, 2);
            if (t == 0)
                atomicAdd(&g_sall[rowBase + wm * 32 + i * 16 + g + h * 8], v);
        }
    // col sums (only off-diagonal tiles)
    if (!diag) {
        #pragma unroll
        for (int j = 0; j < 8; j++)
            #pragma unroll
            for (int bb = 0; bb < 2; bb++) {
                float v = acc[0][j][bb] + acc[0][j][2 + bb] +
                          acc[1][j][bb] + acc[1][j][2 + bb];
                v += __shfl_xor_sync(0xffffffffu, v, 4);
                v += __shfl_xor_sync(0xffffffffu, v, 8);
                v += __shfl_xor_sync(0xffffffffu, v, 16);
                if (g == 0)
                    atomicAdd(&g_sall[colBase + wn * 64 + j * 8 + 2 * t + bb], v);
            }
    }
}

// ---------------- kernel 4: finalize loss ----------------------------------
__global__ void k_final(const void* __restrict__ lab, float* __restrict__ out) {
    __shared__ float ssum[256];
    __shared__ int   scnt[256];
    int tid = threadIdx.x;
    float acc = 0.0f;
    int cnt = 0;
    for (int i = tid; i < N; i += 256) {
        int c = get_label(lab, i);
        int m = g_cnt[c];
        int np = m - 1, nn = N - m;
        if (np > 0 && nn > 0) {
            float sneg = g_sall[i] - g_samesum[i];
            sneg = fmaxf(sneg, 1e-30f);
            float x = g_lsep[i] + logf((float)nn) + logf(sneg) + logf((float)np);
            float sp = (x > 0.0f) ? (x + log1pf(__expf(-x))) : log1pf(__expf(x));
            acc += sp;
            cnt++;
        }
    }
    ssum[tid] = acc; scnt[tid] = cnt;
    __syncthreads();
    for (int s = 128; s > 0; s >>= 1) {
        if (tid < s) { ssum[tid] += ssum[tid + s]; scnt[tid] += scnt[tid + s]; }
        __syncthreads();
    }
    if (tid == 0) out[0] = ssum[0] / fmaxf((float)scnt[0], 1.0f);
}

// ---------------- launch ---------------------------------------------------
extern "C" void kernel_launch(void* const* d_in, const int* in_sizes, int n_in,
                              void* d_out, int out_size) {
    const float* embeds = (const float*)d_in[0];
    const void*  labels = d_in[1];
    float* out = (float*)d_out;
    (void)in_sizes; (void)n_in; (void)out_size;

    cudaFuncSetAttribute(k_main_m, cudaFuncAttributeMaxDynamicSharedMemorySize, SMEM_SZ);

    k_pre<<<2, 256>>>(labels);
    k_norm<<<N / 8, 256>>>(embeds, labels);
    k_class<<<NC, 128>>>();
    k_main_m<<<2080, 256, SMEM_SZ>>>();
    k_final<<<1, 256>>>(labels, out);
}